// round 13
// baseline (speedup 1.0000x reference)
#include <cuda_runtime.h>
#include <cuda_fp16.h>
#include <cstdint>

#define BATCH 4
#define LSEQ  1024
#define DMODEL 1024
#define NH    16
#define DHD   64
#define BHN   (BATCH*NH)        // 64
#define PROJ_ELEMS (BATCH*NH*LSEQ*DHD)
#define LOGIT_ELEMS ((size_t)BHN*LSEQ*LSEQ)
#define WELEMS (DMODEL*DMODEL)

// fp16 intermediates
__device__ __half g_q[PROJ_ELEMS];
__device__ __half g_k[PROJ_ELEMS];
__device__ __half g_v[PROJ_ELEMS];
__device__ __half g_ctx[PROJ_ELEMS];
__device__ __half g_logits[LOGIT_ELEMS];
__device__ float  g_invs[BHN*LSEQ];
// fp16 copies of fp32 inputs/weights
__device__ __half g_hkey[PROJ_ELEMS];
__device__ __half g_hval[PROJ_ELEMS];
__device__ __half g_hqin[PROJ_ELEMS];
__device__ __half g_hwk[WELEMS];
__device__ __half g_hwv[WELEMS];
__device__ __half g_hwq[WELEMS];
__device__ __half g_hwo[WELEMS];

__device__ __forceinline__ uint32_t h2pack(float x, float y) {
    __half2 h = __floats2half2_rn(x, y);
    return *(uint32_t*)&h;
}
__device__ __forceinline__ uint32_t f2tf(float f) {
    uint32_t u;
    asm("cvt.rna.tf32.f32 %0, %1;" : "=r"(u) : "f"(f));
    return u;
}

__device__ __forceinline__ void mma16(float* c, const uint32_t* a, const uint32_t* b) {
    asm volatile(
        "mma.sync.aligned.m16n8k16.row.col.f32.f16.f16.f32 "
        "{%0,%1,%2,%3}, {%4,%5,%6,%7}, {%8,%9}, {%0,%1,%2,%3};"
        : "+f"(c[0]), "+f"(c[1]), "+f"(c[2]), "+f"(c[3])
        : "r"(a[0]), "r"(a[1]), "r"(a[2]), "r"(a[3]), "r"(b[0]), "r"(b[1]));
}
__device__ __forceinline__ void mma8t(float* c, const uint32_t* a, const uint32_t* b) {
    asm volatile(
        "mma.sync.aligned.m16n8k8.row.col.f32.tf32.tf32.f32 "
        "{%0,%1,%2,%3}, {%4,%5,%6,%7}, {%8,%9}, {%0,%1,%2,%3};"
        : "+f"(c[0]), "+f"(c[1]), "+f"(c[2]), "+f"(c[3])
        : "r"(a[0]), "r"(a[1]), "r"(a[2]), "r"(a[3]), "r"(b[0]), "r"(b[1]));
}

__device__ __forceinline__ void ldsm_x4(uint32_t* r, uint32_t a) {
    asm volatile("ldmatrix.sync.aligned.m8n8.x4.shared.b16 {%0,%1,%2,%3}, [%4];"
        : "=r"(r[0]), "=r"(r[1]), "=r"(r[2]), "=r"(r[3]) : "r"(a));
}
__device__ __forceinline__ void ldsm_x4_t(uint32_t* r, uint32_t a) {
    asm volatile("ldmatrix.sync.aligned.m8n8.x4.trans.shared.b16 {%0,%1,%2,%3}, [%4];"
        : "=r"(r[0]), "=r"(r[1]), "=r"(r[2]), "=r"(r[3]) : "r"(a));
}

__device__ __forceinline__ void cpa16(void* smem, const void* gmem) {
    uint32_t s = (uint32_t)__cvta_generic_to_shared(smem);
    asm volatile("cp.async.cg.shared.global [%0], [%1], 16;" :: "r"(s), "l"(gmem) : "memory");
}
template<int N> __device__ __forceinline__ void cp_wait() {
    asm volatile("cp.async.wait_group %0;" :: "n"(N) : "memory");
}
__device__ __forceinline__ void cp_commit() {
    asm volatile("cp.async.commit_group;" ::: "memory");
}

// ---------------------------------------------------------------------------
// Shared GEMM body (unchanged from r12).
// ---------------------------------------------------------------------------
template<class TA, class TB, class TC, int BM, int BN, int WGM, int WGN,
         int AMODE, int BMODE, int CMODE, int EMODE, int STAGES>
__device__ __forceinline__ void gemm_body(
    const TA* __restrict__ Ap, const TB* __restrict__ Bp,
    const float* __restrict__ bias, TC* __restrict__ Cp,
    int K, long long lda, long long ldb, long long ldc,
    float scale, const float* __restrict__ rowscale, char* dynsm)
{
    constexpr int BK  = 64;
    constexpr int NT  = WGM*WGN*32;
    constexpr int WM  = BM/WGM, WN = BN/WGN;
    constexpr int MI  = WM/16,  NI = WN/8;
    constexpr int AIT = BM*8/NT;
    constexpr int BIT = (BMODE==0) ? BN*8/NT : BK*(BN/8)/NT;
    constexpr int LDA_ = BK + 8;
    constexpr int LDB_ = ((BMODE==0)?BK:BN) + 8;
    constexpr int BROWS = (BMODE==0)?BN:BK;
    constexpr int ASTRIDE = BM*LDA_;
    constexpr int BSTRIDE = BROWS*LDB_;
    constexpr int D = STAGES - 1;

    const int tid  = threadIdx.x;
    const int lane = tid & 31;
    const int wid  = tid >> 5;
    const int wm   = (wid % WGM) * WM;
    const int wn   = (wid / WGM) * WN;
    const int bm0  = blockIdx.y * BM;
    const int bn0  = blockIdx.x * BN;

    __half* sA = (__half*)dynsm;
    __half* sB = sA + STAGES*ASTRIDE;

    const int a_row = (lane & 7) + ((lane >> 3) & 1) * 8;
    const int a_k8  = ((lane >> 4) & 1) * 8;
    const int b_row = (lane & 7) + ((lane >> 4) & 1) * 8;
    const int b_k8  = ((lane >> 3) & 1) * 8;
    const int t_k   = (lane & 7) + ((lane >> 3) & 1) * 8;
    const int t_n8  = ((lane >> 4) & 1) * 8;

    auto aptr = [&](int r, int gk) -> const TA* {
        int grow = bm0 + r;
        if (AMODE == 0) {
            return Ap + (long long)grow*lda + gk;
        } else {
            int b = grow >> 10, l = grow & 1023;
            int hh = gk >> 6,  dd = gk & 63;
            return Ap + (long long)(b*NH + hh)*(LSEQ*DHD) + l*DHD + dd;
        }
    };

    float acc[MI][NI][4];
    #pragma unroll
    for (int mi = 0; mi < MI; mi++)
        #pragma unroll
        for (int ni = 0; ni < NI; ni++)
            #pragma unroll
            for (int r = 0; r < 4; r++) acc[mi][ni][r] = 0.f;

    const int T = K / BK;

    auto compute = [&](int s) {
        const uint32_t sAb = (uint32_t)__cvta_generic_to_shared(sA + s*ASTRIDE);
        const uint32_t sBb = (uint32_t)__cvta_generic_to_shared(sB + s*BSTRIDE);
        #pragma unroll
        for (int kk = 0; kk < BK; kk += 16) {
            uint32_t af[MI][4], bf[NI][2];
            #pragma unroll
            for (int mi = 0; mi < MI; mi++)
                ldsm_x4(af[mi], sAb + (((wm + mi*16 + a_row)*LDA_ + kk + a_k8) << 1));
            #pragma unroll
            for (int np = 0; np < NI; np += 2) {
                if (BMODE == 0)
                    ldsm_x4(&bf[np][0], sBb + (((wn + np*8 + b_row)*LDB_ + kk + b_k8) << 1));
                else
                    ldsm_x4_t(&bf[np][0], sBb + (((kk + t_k)*LDB_ + wn + np*8 + t_n8) << 1));
            }
            #pragma unroll
            for (int mi = 0; mi < MI; mi++)
                #pragma unroll
                for (int ni = 0; ni < NI; ni++)
                    mma16(acc[mi][ni], af[mi], bf[ni]);
        }
    };

    auto cpa_tile = [&](int s, int kt) {
        #pragma unroll
        for (int i = 0; i < AIT; i++) {
            int idx = tid + i*NT;
            int r = idx >> 3, c = (idx & 7) << 3;
            cpa16(sA + s*ASTRIDE + r*LDA_ + c, aptr(r, kt*BK + c));
        }
        #pragma unroll
        for (int i = 0; i < BIT; i++) {
            int idx = tid + i*NT;
            if (BMODE == 0) {
                int r = idx >> 3, c = (idx & 7) << 3;
                cpa16(sB + s*BSTRIDE + r*LDB_ + c,
                      Bp + (long long)(bn0 + r)*ldb + kt*BK + c);
            } else {
                int r = idx / (BN/8), c = (idx % (BN/8)) << 3;
                cpa16(sB + s*BSTRIDE + r*LDB_ + c,
                      Bp + (long long)(kt*BK + r)*ldb + bn0 + c);
            }
        }
        cp_commit();
    };

    if constexpr (STAGES == 1) {
        cpa_tile(0, 0);
        cp_wait<0>();
        __syncthreads();
        compute(0);
    } else {
        #pragma unroll
        for (int s = 0; s < D; s++)
            if (s < T) cpa_tile(s, s);
        for (int t = 0; t < T; ++t) {
            if (t + D < T) cp_wait<(D > 0 ? D - 1 : 0)>();
            else           cp_wait<0>();
            __syncthreads();
            if (t + D < T) cpa_tile((t + D) % STAGES, t + D);
            compute(t % STAGES);
        }
    }

    #pragma unroll
    for (int mi = 0; mi < MI; mi++) {
        #pragma unroll
        for (int ni = 0; ni < NI; ni++) {
            int mrow = bm0 + wm + mi*16 + (lane >> 2);
            int ncol = bn0 + wn + ni*8 + ((lane & 3) << 1);
            #pragma unroll
            for (int h2 = 0; h2 < 2; h2++) {
                int r = mrow + h2*8;
                float x = acc[mi][ni][h2*2 + 0];
                float y = acc[mi][ni][h2*2 + 1];
                if (bias) { x += bias[ncol]; y += bias[ncol + 1]; }
                x *= scale; y *= scale;
                long long off;
                if (CMODE == 0) {
                    off = (long long)r*ldc + ncol;
                } else {
                    int b = r >> 10, l = r & 1023;
                    int hh = ncol >> 6, dd = ncol & 63;
                    off = (long long)(b*NH + hh)*(LSEQ*DHD) + l*DHD + dd;
                }
                if (EMODE == 2) {
                    float2 o = __half22float2(*(const __half2*)(Cp + off));
                    float iv = rowscale[r];
                    x = (x + o.x) * iv;
                    y = (y + o.y) * iv;
                }
                if constexpr (sizeof(TC) == 4) {
                    *(float2*)(Cp + off) = make_float2(x, y);
                } else {
                    *(__half2*)(Cp + off) = __floats2half2_rn(x, y);
                }
            }
        }
    }
}

template<class TA, class TB, class TC, int BM, int BN, int WGM, int WGN,
         int AMODE, int BMODE, int CMODE, int EMODE, int STAGES, int MINB>
__global__ void __launch_bounds__(WGM*WGN*32, MINB) gemm_h(
    const TA* __restrict__ A, const TB* __restrict__ B,
    const float* __restrict__ bias, TC* __restrict__ C,
    int K,
    long long lda, long long ldb, long long ldc,
    long long sAz, long long sBz, long long sCz,
    float scale, const float* __restrict__ rowscale)
{
    extern __shared__ char dynsm[];
    const int z = blockIdx.z;
    gemm_body<TA,TB,TC,BM,BN,WGM,WGN,AMODE,BMODE,CMODE,EMODE,STAGES>(
        A + (long long)z*sAz, B + (long long)z*sBz, bias, C + (long long)z*sCz,
        K, lda, ldb, ldc, scale,
        rowscale ? rowscale + (long long)z*LSEQ : nullptr, dynsm);
}

struct P3 {
    const __half* A[3];
    const __half* W[3];
    const float*  b[3];
    __half*       C[3];
    float         s[3];
};
__global__ void __launch_bounds__(512, 2) proj3_kernel(P3 p)
{
    extern __shared__ char dynsm[];
    const int z = blockIdx.z;
    gemm_body<__half,__half,__half,128,128,4,4,0,0,1,0,3>(
        p.A[z], p.W[z], p.b[z], p.C[z],
        DMODEL, DMODEL, DMODEL, DMODEL, p.s[z], nullptr, dynsm);
}

struct Cvt7 {
    const float* s[7];
    __half*      d[7];
    int          n4[7];
};
__global__ void __launch_bounds__(256) cvt7_kernel(Cvt7 c)
{
    int seg = blockIdx.y;
    const float4* src = (const float4*)c.s[seg];
    __half* dst = c.d[seg];
    int n4 = c.n4[seg];
    for (int i = blockIdx.x*blockDim.x + threadIdx.x; i < n4;
         i += gridDim.x*blockDim.x) {
        float4 v = src[i];
        uint2 o = make_uint2(h2pack(v.x, v.y), h2pack(v.z, v.w));
        *(uint2*)(dst + (size_t)i*4) = o;
    }
}

// ---------------------------------------------------------------------------
// Pass 2 v2: tf32 MMA + cp.async 4-stage ring for rel_k/rel_v (fp32 direct),
// smem-staged logits read/write (coalesced), smem-cached mask.
// Block = one q; 512 threads; 16 warps (4m x 4col); chunk = 64 keys; 16 chunks.
// ---------------------------------------------------------------------------
#define NCH   16
#define CH    64
#define SQLD  68   // fp32 words
#define SRLD  68
#define SVLD  72
#define SALD  68
#define SLGLD 72   // halves
#define RING_STAGE_F (CH*SRLD + CH*SVLD)              // 8960 floats
#define P2_OFF_Q   (4*RING_STAGE_F)                   // 35840
#define P2_OFF_AL  (P2_OFF_Q + 64*SQLD)               // +4352
#define P2_OFF_LG  (P2_OFF_AL + 64*SALD)              // +4352
#define P2_OFF_MK  (P2_OFF_LG + (64*SLGLD)/2)         // sLG = 4608 halves = 2304 floats
#define P2_OFF_RS  (P2_OFF_MK + 1024)                 // mask 4096 B = 1024 floats
#define P2_SMEM_BYTES ((P2_OFF_RS + 64) * 4)

__global__ void __launch_bounds__(512) pass2_fused(
    const __half* __restrict__ Qp,
    const float*  __restrict__ relk,
    const float*  __restrict__ relv,
    __half* __restrict__ logits,
    const unsigned char* __restrict__ mask,
    __half* __restrict__ ctx,
    float* __restrict__ invs)
{
    extern __shared__ float smf[];
    float* sRing = smf;
    float* sQ    = smf + P2_OFF_Q;
    float* sAL   = smf + P2_OFF_AL;
    __half* sLG  = (__half*)(smf + P2_OFF_LG);
    unsigned char* sMask = (unsigned char*)(smf + P2_OFF_MK);
    float* rsum  = smf + P2_OFF_RS;

    const int q    = blockIdx.x;
    const int tid  = threadIdx.x;
    const int lane = tid & 31;
    const int wid  = tid >> 5;
    const int wm   = (wid & 3) * 16;    // bh row group
    const int wn   = (wid >> 2) * 16;   // col group (k-chunk cols / d cols)

    const long long LL = (long long)LSEQ * LSEQ;

    // tf32 ldmatrix lane offsets (32-bit elements, validated in r9)
    const int a_row = (lane & 7) + ((lane >> 3) & 1) * 8;
    const int a_col = (lane >> 4) * 4;
    const int b_row = (lane & 7) + ((lane >> 4) & 1) * 8;
    const int b_col = ((lane >> 3) & 1) * 4;

    const float* relkq = relk + (long long)q * (LSEQ*DHD);
    const float* relvq = relv + (long long)q * (LSEQ*DHD);

    auto cpa_chunk = [&](int s, int kc) {
        float* dR = sRing + s*RING_STAGE_F;
        float* dV = dR + CH*SRLD;
        const float* gR = relkq + (long long)kc*CH*DHD;
        const float* gV = relvq + (long long)kc*CH*DHD;
        #pragma unroll
        for (int i = 0; i < 2; i++) {
            int idx = tid + i*512;
            int r = idx >> 4, c = (idx & 15) << 2;
            cpa16(dR + r*SRLD + c, gR + r*DHD + c);
            cpa16(dV + r*SVLD + c, gV + r*DHD + c);
        }
        cp_commit();
    };

    // prologue: 3 chunks in flight
    cpa_chunk(0, 0); cpa_chunk(1, 1); cpa_chunk(2, 2);

    // sQ: fp16 global -> fp32 smem (exact)
    {
        int r = tid >> 3, c = (tid & 7) << 3;
        uint4 v = *(const uint4*)(Qp + (long long)r*(LSEQ*DHD) + (long long)q*DHD + c);
        const __half* hv = (const __half*)&v;
        #pragma unroll
        for (int j = 0; j < 8; j++) sQ[r*SQLD + c + j] = __half2float(hv[j]);
    }
    // mask rows (4 x 1024 B)
    if (tid < 256) {
        int b = tid >> 6, c = (tid & 63) << 4;
        *(uint4*)&sMask[b*1024 + c] =
            *(const uint4*)(mask + ((long long)b*LSEQ + q)*LSEQ + c);
    }
    if (tid < 64) rsum[tid] = 0.f;

    float ctxr[2][4];
    #pragma unroll
    for (int ni = 0; ni < 2; ni++)
        #pragma unroll
        for (int r = 0; r < 4; r++) ctxr[ni][r] = 0.f;
    float rs[2] = {0.f, 0.f};

    const uint32_t sQb  = (uint32_t)__cvta_generic_to_shared(sQ);
    const uint32_t sALb = (uint32_t)__cvta_generic_to_shared(sAL);
    const int rowb = wm + (lane >> 2);

    for (int kc = 0; kc < NCH; kc++) {
        const int k0 = kc * CH;
        const int s  = kc & 3;
        if (kc + 3 < NCH) cp_wait<2>(); else cp_wait<0>();
        __syncthreads();                    // ring stage s ready; prev chunk fully done
        if (kc + 3 < NCH) cpa_chunk((kc + 3) & 3, kc + 3);

        // cooperative logits chunk load -> sLG (coalesced 128B rows)
        {
            int r = tid >> 3, c = (tid & 7) << 3;
            *(uint4*)&sLG[r*SLGLD + c] =
                *(const uint4*)(logits + (long long)r*LL + (long long)q*LSEQ + k0 + c);
        }

        // QR MMA (tf32): S[64 bh][64 k] chunk, contraction d=64
        float S[2][4];
        #pragma unroll
        for (int ni = 0; ni < 2; ni++)
            #pragma unroll
            for (int r = 0; r < 4; r++) S[ni][r] = 0.f;

        const uint32_t sRb = (uint32_t)__cvta_generic_to_shared(sRing + s*RING_STAGE_F);
        #pragma unroll
        for (int kk = 0; kk < 64; kk += 8) {
            uint32_t af[4], bf[4];
            ldsm_x4(af, sQb + (((wm + a_row)*SQLD + kk + a_col) << 2));
            ldsm_x4(bf, sRb + (((wn + b_row)*SRLD + kk + b_col) << 2));
            #pragma unroll
            for (int j = 0; j < 4; j++) bf[j] = f2tf(__uint_as_float(bf[j]));
            mma8t(S[0], af, &bf[0]);
            mma8t(S[1], af, &bf[2]);
        }
        __syncthreads();                    // sLG visible

        // combine + mask + exp; alpha -> sAL (fp16-rounded values as fp32)
        #pragma unroll
        for (int ni = 0; ni < 2; ni++) {
            int colL = wn + ni*8 + ((lane & 3) << 1);
            #pragma unroll
            for (int h2 = 0; h2 < 2; h2++) {
                int row = rowb + h2*8;
                uint32_t lw = *(const uint32_t*)&sLG[row*SLGLD + colL];
                float2 lg = __half22float2(*(const __half2*)&lw);
                uchar2 mm = *(const uchar2*)&sMask[(row >> 4)*1024 + k0 + colL];
                float vx = S[ni][h2*2 + 0] + lg.x;
                float vy = S[ni][h2*2 + 1] + lg.y;
                if (mm.x) vx = -10000.f;
                if (mm.y) vy = -10000.f;
                float ex = __expf(vx);
                float ey = __expf(vy);
                rs[h2] += ex + ey;
                __half2 eh = __floats2half2_rn(ex, ey);
                float2 ef = __half22float2(eh);
                *(float2*)&sAL[row*SALD + colL] = ef;
            }
        }
        __syncthreads();                    // sAL complete

        // alpha writeback (coalesced STG.128 from sAL)
        {
            int r = tid >> 3, c = (tid & 7) << 3;
            float4 v0 = *(const float4*)&sAL[r*SALD + c];
            float4 v1 = *(const float4*)&sAL[r*SALD + c + 4];
            uint4 o = make_uint4(h2pack(v0.x, v0.y), h2pack(v0.z, v0.w),
                                 h2pack(v1.x, v1.y), h2pack(v1.z, v1.w));
            *(uint4*)(logits + (long long)r*LL + (long long)q*LSEQ + k0 + c) = o;
        }

        // AR MMA (tf32): ctxr += alpha'[64][64] * relv_chunk[64][64]
        const float* sVp = sRing + s*RING_STAGE_F + CH*SRLD;
        #pragma unroll
        for (int kk = 0; kk < 64; kk += 8) {
            uint32_t af[4], bf[2][2];
            ldsm_x4(af, sALb + (((wm + a_row)*SALD + kk + a_col) << 2));
            int c0 = kk + (lane & 3);
            #pragma unroll
            for (int ni = 0; ni < 2; ni++) {
                int n0 = wn + ni*8 + (lane >> 2);
                bf[ni][0] = f2tf(sVp[c0*SVLD + n0]);
                bf[ni][1] = f2tf(sVp[(c0 + 4)*SVLD + n0]);
            }
            mma8t(ctxr[0], af, bf[0]);
            mma8t(ctxr[1], af, bf[1]);
        }
    }

    // row sums -> invs
    #pragma unroll
    for (int h2 = 0; h2 < 2; h2++) {
        float v = rs[h2];
        v += __shfl_xor_sync(0xffffffffu, v, 1);
        v += __shfl_xor_sync(0xffffffffu, v, 2);
        if ((lane & 3) == 0)
            atomicAdd(&rsum[wm + (lane >> 2) + h2*8], v);
    }
    __syncthreads();
    if (tid < 64) invs[(long long)tid*LSEQ + q] = 1.f / rsum[tid];

    // unnormalized AR' -> ctx[bh][q][d] (fp16)
    #pragma unroll
    for (int ni = 0; ni < 2; ni++) {
        #pragma unroll
        for (int h2 = 0; h2 < 2; h2++) {
            int row = wm + (lane >> 2) + h2*8;
            int col = wn + ni*8 + ((lane & 3) << 1);
            *(__half2*)(ctx + (long long)row*(LSEQ*DHD) + (long long)q*DHD + col) =
                __floats2half2_rn(ctxr[ni][h2*2 + 0], ctxr[ni][h2*2 + 1]);
        }
    }
}

extern "C" void kernel_launch(void* const* d_in, const int* in_sizes, int n_in,
                              void* d_out, int out_size)
{
    const float* key   = (const float*)d_in[0];
    const float* value = (const float*)d_in[1];
    const float* query = (const float*)d_in[2];
    const unsigned char* mask = (const unsigned char*)d_in[3];
    const float* rel_k = (const float*)d_in[4];
    const float* rel_v = (const float*)d_in[5];
    const float* Wk = (const float*)d_in[6];
    const float* bk = (const float*)d_in[7];
    const float* Wv = (const float*)d_in[8];
    const float* bv = (const float*)d_in[9];
    const float* Wq = (const float*)d_in[10];
    const float* bq = (const float*)d_in[11];
    const float* Wo = (const float*)d_in[12];
    const float* bo = (const float*)d_in[13];
    float* out = (float*)d_out;

    __half *pq, *pk, *pv, *pctx, *plog;
    __half *hkey, *hval, *hqin, *hwk, *hwv, *hwq, *hwo;
    float *pinvs;
    cudaGetSymbolAddress((void**)&pq,    g_q);
    cudaGetSymbolAddress((void**)&pk,    g_k);
    cudaGetSymbolAddress((void**)&pv,    g_v);
    cudaGetSymbolAddress((void**)&pctx,  g_ctx);
    cudaGetSymbolAddress((void**)&plog,  g_logits);
    cudaGetSymbolAddress((void**)&pinvs, g_invs);
    cudaGetSymbolAddress((void**)&hkey,  g_hkey);
    cudaGetSymbolAddress((void**)&hval,  g_hval);
    cudaGetSymbolAddress((void**)&hqin,  g_hqin);
    cudaGetSymbolAddress((void**)&hwk,   g_hwk);
    cudaGetSymbolAddress((void**)&hwv,   g_hwv);
    cudaGetSymbolAddress((void**)&hwq,   g_hwq);
    cudaGetSymbolAddress((void**)&hwo,   g_hwo);

    const long long LL = (long long)LSEQ * LSEQ;
    const long long LD = (long long)LSEQ * DHD;

    constexpr int P3_SMEM  = 3 * (128*72 + 128*72) * 2;   // 110,592 B
    constexpr int QK_SMEM  = (128*72 + 128*72) * 2;       //  36,864 B
    constexpr int AV_SMEM  = 4 * (128*72 + 64*72) * 2;    // 110,592 B
    constexpr int OUT_SMEM = 3 * (128*72 + 128*72) * 2;   // 110,592 B

    auto qk_fn  = gemm_h<__half,__half,__half,128,128,4,4,0,0,0,0,1,2>;
    auto av_fn  = gemm_h<__half,__half,__half,128,64,8,2,0,1,0,2,4,2>;
    auto out_fn = gemm_h<__half,__half,float,128,128,4,4,1,0,0,0,3,2>;

    static int attr_done = 0;
    if (!attr_done) {
        cudaFuncSetAttribute(pass2_fused,
            cudaFuncAttributeMaxDynamicSharedMemorySize, P2_SMEM_BYTES);
        cudaFuncSetAttribute(proj3_kernel,
            cudaFuncAttributeMaxDynamicSharedMemorySize, P3_SMEM);
        cudaFuncSetAttribute(av_fn,
            cudaFuncAttributeMaxDynamicSharedMemorySize, AV_SMEM);
        cudaFuncSetAttribute(out_fn,
            cudaFuncAttributeMaxDynamicSharedMemorySize, OUT_SMEM);
        attr_done = 1;
    }

    // 0: fp32 -> fp16 conversion of inputs + weights
    Cvt7 cv;
    cv.s[0] = key;   cv.d[0] = hkey; cv.n4[0] = PROJ_ELEMS/4;
    cv.s[1] = value; cv.d[1] = hval; cv.n4[1] = PROJ_ELEMS/4;
    cv.s[2] = query; cv.d[2] = hqin; cv.n4[2] = PROJ_ELEMS/4;
    cv.s[3] = Wk;    cv.d[3] = hwk;  cv.n4[3] = WELEMS/4;
    cv.s[4] = Wv;    cv.d[4] = hwv;  cv.n4[4] = WELEMS/4;
    cv.s[5] = Wq;    cv.d[5] = hwq;  cv.n4[5] = WELEMS/4;
    cv.s[6] = Wo;    cv.d[6] = hwo;  cv.n4[6] = WELEMS/4;
    cvt7_kernel<<<dim3(512,7,1), 256>>>(cv);

    // 1: merged QKV projections
    P3 p;
    p.A[0] = hkey; p.W[0] = hwk; p.b[0] = bk; p.C[0] = pk; p.s[0] = 1.0f;
    p.A[1] = hval; p.W[1] = hwv; p.b[1] = bv; p.C[1] = pv; p.s[1] = 1.0f;
    p.A[2] = hqin; p.W[2] = hwq; p.b[2] = bq; p.C[2] = pq; p.s[2] = 0.125f;
    proj3_kernel<<<dim3(8,32,3), 512, P3_SMEM>>>(p);

    // 2: QK logits = Q·K^T
    qk_fn<<<dim3(8,8,BHN), 512, QK_SMEM>>>(
        pq, pk, nullptr, plog, DHD,
        DHD, DHD, LSEQ,
        LD, LD, LL,
        1.0f, nullptr);

    // 3: fused QR + mask + softmax(no-max) + AR  (tf32 + cp.async ring)
    pass2_fused<<<1024, 512, P2_SMEM_BYTES>>>(pq, rel_k, rel_v, plog, mask, pctx, pinvs);

    // 4: AV: ctx = (alpha'·V + AR') * inv_s
    av_fn<<<dim3(1,8,BHN), 512, AV_SMEM>>>(
        plog, pv, nullptr, pctx, LSEQ,
        LSEQ, DHD, DHD,
        LL, LD, LD,
        1.0f, pinvs);

    // 5: out = ctx @ Wo^T + bo
    out_fn<<<dim3(8,32,1), 512, OUT_SMEM>>>(
        pctx, hwo, bo, out, DMODEL,
        0, DMODEL, DMODEL,
        0, 0, 0,
        1.0f, nullptr);
}

// round 14
// speedup vs baseline: 1.2701x; 1.2701x over previous
#include <cuda_runtime.h>
#include <cuda_fp16.h>
#include <cstdint>

#define BATCH 4
#define LSEQ  1024
#define DMODEL 1024
#define NH    16
#define DHD   64
#define BHN   (BATCH*NH)        // 64
#define PROJ_ELEMS (BATCH*NH*LSEQ*DHD)
#define LOGIT_ELEMS ((size_t)BHN*LSEQ*LSEQ)
#define WELEMS (DMODEL*DMODEL)

// fp16 intermediates
__device__ __half g_q[PROJ_ELEMS];
__device__ __half g_k[PROJ_ELEMS];
__device__ __half g_v[PROJ_ELEMS];
__device__ __half g_ctx[PROJ_ELEMS];
__device__ __half g_logits[LOGIT_ELEMS];
__device__ float  g_invs[BHN*LSEQ];
// fp16 copies of fp32 inputs/weights
__device__ __half g_hkey[PROJ_ELEMS];
__device__ __half g_hval[PROJ_ELEMS];
__device__ __half g_hqin[PROJ_ELEMS];
__device__ __half g_hwk[WELEMS];
__device__ __half g_hwv[WELEMS];
__device__ __half g_hwq[WELEMS];
__device__ __half g_hwo[WELEMS];

__device__ __forceinline__ uint32_t h2pack(float x, float y) {
    __half2 h = __floats2half2_rn(x, y);
    return *(uint32_t*)&h;
}

__device__ __forceinline__ void mma16(float* c, const uint32_t* a, const uint32_t* b) {
    asm volatile(
        "mma.sync.aligned.m16n8k16.row.col.f32.f16.f16.f32 "
        "{%0,%1,%2,%3}, {%4,%5,%6,%7}, {%8,%9}, {%0,%1,%2,%3};"
        : "+f"(c[0]), "+f"(c[1]), "+f"(c[2]), "+f"(c[3])
        : "r"(a[0]), "r"(a[1]), "r"(a[2]), "r"(a[3]), "r"(b[0]), "r"(b[1]));
}

__device__ __forceinline__ void ldsm_x4(uint32_t* r, uint32_t a) {
    asm volatile("ldmatrix.sync.aligned.m8n8.x4.shared.b16 {%0,%1,%2,%3}, [%4];"
        : "=r"(r[0]), "=r"(r[1]), "=r"(r[2]), "=r"(r[3]) : "r"(a));
}
__device__ __forceinline__ void ldsm_x4_t(uint32_t* r, uint32_t a) {
    asm volatile("ldmatrix.sync.aligned.m8n8.x4.trans.shared.b16 {%0,%1,%2,%3}, [%4];"
        : "=r"(r[0]), "=r"(r[1]), "=r"(r[2]), "=r"(r[3]) : "r"(a));
}

__device__ __forceinline__ void cpa16(void* smem, const void* gmem) {
    uint32_t s = (uint32_t)__cvta_generic_to_shared(smem);
    asm volatile("cp.async.cg.shared.global [%0], [%1], 16;" :: "r"(s), "l"(gmem) : "memory");
}
template<int N> __device__ __forceinline__ void cp_wait() {
    asm volatile("cp.async.wait_group %0;" :: "n"(N) : "memory");
}
__device__ __forceinline__ void cp_commit() {
    asm volatile("cp.async.commit_group;" ::: "memory");
}

// ---------------------------------------------------------------------------
// Shared GEMM body (identical to r12).
// ---------------------------------------------------------------------------
template<class TA, class TB, class TC, int BM, int BN, int WGM, int WGN,
         int AMODE, int BMODE, int CMODE, int EMODE, int STAGES>
__device__ __forceinline__ void gemm_body(
    const TA* __restrict__ Ap, const TB* __restrict__ Bp,
    const float* __restrict__ bias, TC* __restrict__ Cp,
    int K, long long lda, long long ldb, long long ldc,
    float scale, const float* __restrict__ rowscale, char* dynsm)
{
    constexpr int BK  = 64;
    constexpr int NT  = WGM*WGN*32;
    constexpr int WM  = BM/WGM, WN = BN/WGN;
    constexpr int MI  = WM/16,  NI = WN/8;
    constexpr int AIT = BM*8/NT;
    constexpr int BIT = (BMODE==0) ? BN*8/NT : BK*(BN/8)/NT;
    constexpr int LDA_ = BK + 8;
    constexpr int LDB_ = ((BMODE==0)?BK:BN) + 8;
    constexpr int BROWS = (BMODE==0)?BN:BK;
    constexpr int ASTRIDE = BM*LDA_;
    constexpr int BSTRIDE = BROWS*LDB_;
    constexpr int D = STAGES - 1;

    const int tid  = threadIdx.x;
    const int lane = tid & 31;
    const int wid  = tid >> 5;
    const int wm   = (wid % WGM) * WM;
    const int wn   = (wid / WGM) * WN;
    const int bm0  = blockIdx.y * BM;
    const int bn0  = blockIdx.x * BN;

    __half* sA = (__half*)dynsm;
    __half* sB = sA + STAGES*ASTRIDE;

    const int a_row = (lane & 7) + ((lane >> 3) & 1) * 8;
    const int a_k8  = ((lane >> 4) & 1) * 8;
    const int b_row = (lane & 7) + ((lane >> 4) & 1) * 8;
    const int b_k8  = ((lane >> 3) & 1) * 8;
    const int t_k   = (lane & 7) + ((lane >> 3) & 1) * 8;
    const int t_n8  = ((lane >> 4) & 1) * 8;

    auto aptr = [&](int r, int gk) -> const TA* {
        int grow = bm0 + r;
        if (AMODE == 0) {
            return Ap + (long long)grow*lda + gk;
        } else {
            int b = grow >> 10, l = grow & 1023;
            int hh = gk >> 6,  dd = gk & 63;
            return Ap + (long long)(b*NH + hh)*(LSEQ*DHD) + l*DHD + dd;
        }
    };

    float acc[MI][NI][4];
    #pragma unroll
    for (int mi = 0; mi < MI; mi++)
        #pragma unroll
        for (int ni = 0; ni < NI; ni++)
            #pragma unroll
            for (int r = 0; r < 4; r++) acc[mi][ni][r] = 0.f;

    const int T = K / BK;

    auto compute = [&](int s) {
        const uint32_t sAb = (uint32_t)__cvta_generic_to_shared(sA + s*ASTRIDE);
        const uint32_t sBb = (uint32_t)__cvta_generic_to_shared(sB + s*BSTRIDE);
        #pragma unroll
        for (int kk = 0; kk < BK; kk += 16) {
            uint32_t af[MI][4], bf[NI][2];
            #pragma unroll
            for (int mi = 0; mi < MI; mi++)
                ldsm_x4(af[mi], sAb + (((wm + mi*16 + a_row)*LDA_ + kk + a_k8) << 1));
            #pragma unroll
            for (int np = 0; np < NI; np += 2) {
                if (BMODE == 0)
                    ldsm_x4(&bf[np][0], sBb + (((wn + np*8 + b_row)*LDB_ + kk + b_k8) << 1));
                else
                    ldsm_x4_t(&bf[np][0], sBb + (((kk + t_k)*LDB_ + wn + np*8 + t_n8) << 1));
            }
            #pragma unroll
            for (int mi = 0; mi < MI; mi++)
                #pragma unroll
                for (int ni = 0; ni < NI; ni++)
                    mma16(acc[mi][ni], af[mi], bf[ni]);
        }
    };

    auto cpa_tile = [&](int s, int kt) {
        #pragma unroll
        for (int i = 0; i < AIT; i++) {
            int idx = tid + i*NT;
            int r = idx >> 3, c = (idx & 7) << 3;
            cpa16(sA + s*ASTRIDE + r*LDA_ + c, aptr(r, kt*BK + c));
        }
        #pragma unroll
        for (int i = 0; i < BIT; i++) {
            int idx = tid + i*NT;
            if (BMODE == 0) {
                int r = idx >> 3, c = (idx & 7) << 3;
                cpa16(sB + s*BSTRIDE + r*LDB_ + c,
                      Bp + (long long)(bn0 + r)*ldb + kt*BK + c);
            } else {
                int r = idx / (BN/8), c = (idx % (BN/8)) << 3;
                cpa16(sB + s*BSTRIDE + r*LDB_ + c,
                      Bp + (long long)(kt*BK + r)*ldb + bn0 + c);
            }
        }
        cp_commit();
    };

    if constexpr (STAGES == 1) {
        cpa_tile(0, 0);
        cp_wait<0>();
        __syncthreads();
        compute(0);
    } else {
        #pragma unroll
        for (int s = 0; s < D; s++)
            if (s < T) cpa_tile(s, s);
        for (int t = 0; t < T; ++t) {
            if (t + D < T) cp_wait<(D > 0 ? D - 1 : 0)>();
            else           cp_wait<0>();
            __syncthreads();
            if (t + D < T) cpa_tile((t + D) % STAGES, t + D);
            compute(t % STAGES);
        }
    }

    #pragma unroll
    for (int mi = 0; mi < MI; mi++) {
        #pragma unroll
        for (int ni = 0; ni < NI; ni++) {
            int mrow = bm0 + wm + mi*16 + (lane >> 2);
            int ncol = bn0 + wn + ni*8 + ((lane & 3) << 1);
            #pragma unroll
            for (int h2 = 0; h2 < 2; h2++) {
                int r = mrow + h2*8;
                float x = acc[mi][ni][h2*2 + 0];
                float y = acc[mi][ni][h2*2 + 1];
                if (bias) { x += bias[ncol]; y += bias[ncol + 1]; }
                x *= scale; y *= scale;
                long long off;
                if (CMODE == 0) {
                    off = (long long)r*ldc + ncol;
                } else {
                    int b = r >> 10, l = r & 1023;
                    int hh = ncol >> 6, dd = ncol & 63;
                    off = (long long)(b*NH + hh)*(LSEQ*DHD) + l*DHD + dd;
                }
                if (EMODE == 2) {
                    float2 o = __half22float2(*(const __half2*)(Cp + off));
                    float iv = rowscale[r];
                    x = (x + o.x) * iv;
                    y = (y + o.y) * iv;
                }
                if constexpr (sizeof(TC) == 4) {
                    *(float2*)(Cp + off) = make_float2(x, y);
                } else {
                    *(__half2*)(Cp + off) = __floats2half2_rn(x, y);
                }
            }
        }
    }
}

template<class TA, class TB, class TC, int BM, int BN, int WGM, int WGN,
         int AMODE, int BMODE, int CMODE, int EMODE, int STAGES, int MINB>
__global__ void __launch_bounds__(WGM*WGN*32, MINB) gemm_h(
    const TA* __restrict__ A, const TB* __restrict__ B,
    const float* __restrict__ bias, TC* __restrict__ C,
    int K,
    long long lda, long long ldb, long long ldc,
    long long sAz, long long sBz, long long sCz,
    float scale, const float* __restrict__ rowscale)
{
    extern __shared__ char dynsm[];
    const int z = blockIdx.z;
    gemm_body<TA,TB,TC,BM,BN,WGM,WGN,AMODE,BMODE,CMODE,EMODE,STAGES>(
        A + (long long)z*sAz, B + (long long)z*sBz, bias, C + (long long)z*sCz,
        K, lda, ldb, ldc, scale,
        rowscale ? rowscale + (long long)z*LSEQ : nullptr, dynsm);
}

struct P3 {
    const __half* A[3];
    const __half* W[3];
    const float*  b[3];
    __half*       C[3];
    float         s[3];
};
__global__ void __launch_bounds__(512, 2) proj3_kernel(P3 p)
{
    extern __shared__ char dynsm[];
    const int z = blockIdx.z;
    gemm_body<__half,__half,__half,128,128,4,4,0,0,1,0,3>(
        p.A[z], p.W[z], p.b[z], p.C[z],
        DMODEL, DMODEL, DMODEL, DMODEL, p.s[z], nullptr, dynsm);
}

struct Cvt7 {
    const float* s[7];
    __half*      d[7];
    int          n4[7];
};
__global__ void __launch_bounds__(256) cvt7_kernel(Cvt7 c)
{
    int seg = blockIdx.y;
    const float4* src = (const float4*)c.s[seg];
    __half* dst = c.d[seg];
    int n4 = c.n4[seg];
    for (int i = blockIdx.x*blockDim.x + threadIdx.x; i < n4;
         i += gridDim.x*blockDim.x) {
        float4 v = src[i];
        uint2 o = make_uint2(h2pack(v.x, v.y), h2pack(v.z, v.w));
        *(uint2*)(dst + (size_t)i*4) = o;
    }
}

// ---------------------------------------------------------------------------
// Pass 2 (r12 skeleton + coalesced logits staging):
// per-q fused QR + QK-add + mask + max-free softmax + AR. fp16 MMA,
// register prefetch of next rel chunk; logits chunk staged via cp.async into
// sLG (coalesced); alpha written back coalesced from sAL; mask cached in smem.
// ---------------------------------------------------------------------------
#define SQ_LD 72
#define SR_LD 72
#define SV_LD 72
#define SAL_LD 136
#define SLG_LD 136
#define P2_HALVES (64*SQ_LD + 128*SR_LD + 128*SV_LD + 64*SAL_LD + 64*SLG_LD)
#define P2_SMEM_BYTES (P2_HALVES*2 + 4096 + 256)

__global__ void __launch_bounds__(512) pass2_fused(
    const __half* __restrict__ Qp,
    const float*  __restrict__ relk,
    const float*  __restrict__ relv,
    __half* __restrict__ logits,
    const unsigned char* __restrict__ mask,
    __half* __restrict__ ctx,
    float* __restrict__ invs)
{
    extern __shared__ __half smh[];
    __half (*sQ)[SQ_LD]   = (__half(*)[SQ_LD])smh;
    __half (*sR)[SR_LD]   = (__half(*)[SR_LD])(smh + 64*SQ_LD);
    __half (*sV)[SV_LD]   = (__half(*)[SV_LD])(smh + 64*SQ_LD + 128*SR_LD);
    __half (*sAL)[SAL_LD] = (__half(*)[SAL_LD])(smh + 64*SQ_LD + 128*SR_LD + 128*SV_LD);
    __half (*sLG)[SLG_LD] = (__half(*)[SLG_LD])(smh + 64*SQ_LD + 128*SR_LD + 128*SV_LD + 64*SAL_LD);
    unsigned char* sMask = (unsigned char*)(smh + P2_HALVES);
    float* rsum = (float*)(sMask + 4096);

    const int q    = blockIdx.x;
    const int tid  = threadIdx.x;
    const int lane = tid & 31;
    const int wid  = tid >> 5;
    const int wm   = (wid & 3) * 16;
    const int wn   = (wid >> 2) * 32;
    const int wnA  = (wid >> 2) * 16;

    const long long LL = (long long)LSEQ * LSEQ;

    const uint32_t sQ_base  = (uint32_t)__cvta_generic_to_shared(&sQ[0][0]);
    const uint32_t sR_base  = (uint32_t)__cvta_generic_to_shared(&sR[0][0]);
    const uint32_t sV_base  = (uint32_t)__cvta_generic_to_shared(&sV[0][0]);
    const uint32_t sAL_base = (uint32_t)__cvta_generic_to_shared(&sAL[0][0]);
    const int a_row = (lane & 7) + ((lane >> 3) & 1) * 8;
    const int a_k8  = ((lane >> 4) & 1) * 8;
    const int b_row = (lane & 7) + ((lane >> 4) & 1) * 8;
    const int b_k8  = ((lane >> 3) & 1) * 8;
    const int t_k   = (lane & 7) + ((lane >> 3) & 1) * 8;
    const int t_n8  = ((lane >> 4) & 1) * 8;

    {
        int r = tid >> 3, c = (tid & 7) << 3;
        *(uint4*)&sQ[r][c] =
            *(const uint4*)(Qp + (long long)r*(LSEQ*DHD) + (long long)q*DHD + c);
    }
    // mask rows for the 4 batches (4 x 1024 B), cached once
    if (tid < 256) {
        int b = tid >> 6, c = (tid & 63) << 4;
        *(uint4*)&sMask[b*1024 + c] =
            *(const uint4*)(mask + ((long long)b*LSEQ + q)*LSEQ + c);
    }
    if (tid < 64) rsum[tid] = 0.f;

    const float* relkq = relk + (long long)q * (LSEQ*DHD);
    const float* relvq = relv + (long long)q * (LSEQ*DHD);

    float4 fR[4], fV[4];
    auto ldchunk = [&](int kc) {
        #pragma unroll
        for (int i = 0; i < 2; i++) {
            int idx = tid + i*512;
            int r = idx >> 3, c = (idx & 7) << 3;
            const float* pk_ = relkq + (long long)(kc*128 + r)*DHD + c;
            const float* pv_ = relvq + (long long)(kc*128 + r)*DHD + c;
            fR[2*i]   = *(const float4*)pk_;
            fR[2*i+1] = *(const float4*)(pk_ + 4);
            fV[2*i]   = *(const float4*)pv_;
            fV[2*i+1] = *(const float4*)(pv_ + 4);
        }
    };
    auto stchunk = [&]() {
        #pragma unroll
        for (int i = 0; i < 2; i++) {
            int idx = tid + i*512;
            int r = idx >> 3, c = (idx & 7) << 3;
            *(uint4*)&sR[r][c] = make_uint4(
                h2pack(fR[2*i].x, fR[2*i].y),     h2pack(fR[2*i].z, fR[2*i].w),
                h2pack(fR[2*i+1].x, fR[2*i+1].y), h2pack(fR[2*i+1].z, fR[2*i+1].w));
            *(uint4*)&sV[r][c] = make_uint4(
                h2pack(fV[2*i].x, fV[2*i].y),     h2pack(fV[2*i].z, fV[2*i].w),
                h2pack(fV[2*i+1].x, fV[2*i+1].y), h2pack(fV[2*i+1].z, fV[2*i+1].w));
        }
    };

    float ctxr[2][4];
    #pragma unroll
    for (int ni = 0; ni < 2; ni++)
        #pragma unroll
        for (int r = 0; r < 4; r++) ctxr[ni][r] = 0.f;
    float rs[2] = {0.f, 0.f};

    ldchunk(0);

    for (int kc = 0; kc < 8; kc++) {
        const int k0 = kc * 128;
        __syncthreads();            // prev MMAs done reading sR/sV/sAL; sLG consumed
        stchunk();
        // stage logits chunk via cp.async (coalesced 16B), lands during QR MMA
        #pragma unroll
        for (int i = 0; i < 2; i++) {
            int idx = tid + i*512;
            int r = idx >> 4, c8 = (idx & 15) << 3;
            cpa16(&sLG[r][c8],
                  logits + (long long)r*LL + (long long)q*LSEQ + k0 + c8);
        }
        cp_commit();
        __syncthreads();            // sR/sV ready
        if (kc + 1 < 8) ldchunk(kc + 1);   // register prefetch of next rel chunk

        const int rowb = wm + (lane >> 2);

        // QR MMA: S[64][128] chunk (contraction d=64)
        float S[4][4];
        #pragma unroll
        for (int ni = 0; ni < 4; ni++)
            #pragma unroll
            for (int r = 0; r < 4; r++) S[ni][r] = 0.f;

        #pragma unroll
        for (int kk = 0; kk < 64; kk += 16) {
            uint32_t af[4], bf[4][2];
            ldsm_x4(af, sQ_base + (((wm + a_row)*SQ_LD + kk + a_k8) << 1));
            #pragma unroll
            for (int np = 0; np < 4; np += 2)
                ldsm_x4(&bf[np][0],
                    sR_base + (((wn + np*8 + b_row)*SR_LD + kk + b_k8) << 1));
            #pragma unroll
            for (int ni = 0; ni < 4; ni++)
                mma16(S[ni], af, bf[ni]);
        }

        cp_wait<0>();
        __syncthreads();            // sLG visible to all warps

        // combine + mask + exp; alpha -> sAL only
        #pragma unroll
        for (int ni = 0; ni < 4; ni++) {
            int colL = wn + ni*8 + ((lane & 3) << 1);
            #pragma unroll
            for (int h2 = 0; h2 < 2; h2++) {
                int row = rowb + h2*8;
                float2 lg = __half22float2(*(const __half2*)&sLG[row][colL]);
                uchar2 mm = *(const uchar2*)&sMask[(row >> 4)*1024 + k0 + colL];
                float vx = S[ni][h2*2 + 0] + lg.x;
                float vy = S[ni][h2*2 + 1] + lg.y;
                if (mm.x) vx = -10000.f;
                if (mm.y) vy = -10000.f;
                float ex = __expf(vx);
                float ey = __expf(vy);
                rs[h2] += ex + ey;
                *(__half2*)&sAL[row][colL] = __floats2half2_rn(ex, ey);
            }
        }
        __syncthreads();            // sAL complete

        // alpha writeback (coalesced STG.128 from sAL), overlaps AR MMA
        #pragma unroll
        for (int i = 0; i < 2; i++) {
            int idx = tid + i*512;
            int r = idx >> 4, c8 = (idx & 15) << 3;
            *(uint4*)(logits + (long long)r*LL + (long long)q*LSEQ + k0 + c8) =
                *(const uint4*)&sAL[r][c8];
        }

        // AR MMA: ctxr += alpha'[64][128] * relv[q][k0:k0+128][:]
        #pragma unroll
        for (int kk = 0; kk < 128; kk += 16) {
            uint32_t af[4], bf[2][2];
            ldsm_x4(af, sAL_base + (((wm + a_row)*SAL_LD + kk + a_k8) << 1));
            ldsm_x4_t(&bf[0][0], sV_base + (((kk + t_k)*SV_LD + wnA + t_n8) << 1));
            #pragma unroll
            for (int ni = 0; ni < 2; ni++)
                mma16(ctxr[ni], af, bf[ni]);
        }
    }

    #pragma unroll
    for (int h2 = 0; h2 < 2; h2++) {
        float v = rs[h2];
        v += __shfl_xor_sync(0xffffffffu, v, 1);
        v += __shfl_xor_sync(0xffffffffu, v, 2);
        if ((lane & 3) == 0)
            atomicAdd(&rsum[wm + (lane >> 2) + h2*8], v);
    }
    __syncthreads();
    if (tid < 64) invs[(long long)tid*LSEQ + q] = 1.f / rsum[tid];

    #pragma unroll
    for (int ni = 0; ni < 2; ni++) {
        #pragma unroll
        for (int h2 = 0; h2 < 2; h2++) {
            int row = wm + (lane >> 2) + h2*8;
            int col = wnA + ni*8 + ((lane & 3) << 1);
            *(__half2*)(ctx + (long long)row*(LSEQ*DHD) + (long long)q*DHD + col) =
                __floats2half2_rn(ctxr[ni][h2*2 + 0], ctxr[ni][h2*2 + 1]);
        }
    }
}

extern "C" void kernel_launch(void* const* d_in, const int* in_sizes, int n_in,
                              void* d_out, int out_size)
{
    const float* key   = (const float*)d_in[0];
    const float* value = (const float*)d_in[1];
    const float* query = (const float*)d_in[2];
    const unsigned char* mask = (const unsigned char*)d_in[3];
    const float* rel_k = (const float*)d_in[4];
    const float* rel_v = (const float*)d_in[5];
    const float* Wk = (const float*)d_in[6];
    const float* bk = (const float*)d_in[7];
    const float* Wv = (const float*)d_in[8];
    const float* bv = (const float*)d_in[9];
    const float* Wq = (const float*)d_in[10];
    const float* bq = (const float*)d_in[11];
    const float* Wo = (const float*)d_in[12];
    const float* bo = (const float*)d_in[13];
    float* out = (float*)d_out;

    __half *pq, *pk, *pv, *pctx, *plog;
    __half *hkey, *hval, *hqin, *hwk, *hwv, *hwq, *hwo;
    float *pinvs;
    cudaGetSymbolAddress((void**)&pq,    g_q);
    cudaGetSymbolAddress((void**)&pk,    g_k);
    cudaGetSymbolAddress((void**)&pv,    g_v);
    cudaGetSymbolAddress((void**)&pctx,  g_ctx);
    cudaGetSymbolAddress((void**)&plog,  g_logits);
    cudaGetSymbolAddress((void**)&pinvs, g_invs);
    cudaGetSymbolAddress((void**)&hkey,  g_hkey);
    cudaGetSymbolAddress((void**)&hval,  g_hval);
    cudaGetSymbolAddress((void**)&hqin,  g_hqin);
    cudaGetSymbolAddress((void**)&hwk,   g_hwk);
    cudaGetSymbolAddress((void**)&hwv,   g_hwv);
    cudaGetSymbolAddress((void**)&hwq,   g_hwq);
    cudaGetSymbolAddress((void**)&hwo,   g_hwo);

    const long long LL = (long long)LSEQ * LSEQ;
    const long long LD = (long long)LSEQ * DHD;

    constexpr int P3_SMEM  = 3 * (128*72 + 128*72) * 2;   // 110,592 B
    constexpr int QK_SMEM  = (128*72 + 128*72) * 2;       //  36,864 B
    constexpr int AV_SMEM  = 4 * (128*72 + 64*72) * 2;    // 110,592 B
    constexpr int OUT_SMEM = 3 * (128*72 + 128*72) * 2;   // 110,592 B

    auto qk_fn  = gemm_h<__half,__half,__half,128,128,4,4,0,0,0,0,1,2>;
    auto av_fn  = gemm_h<__half,__half,__half,128,64,8,2,0,1,0,2,4,2>;
    auto out_fn = gemm_h<__half,__half,float,128,128,4,4,1,0,0,0,3,2>;

    static int attr_done = 0;
    if (!attr_done) {
        cudaFuncSetAttribute(pass2_fused,
            cudaFuncAttributeMaxDynamicSharedMemorySize, P2_SMEM_BYTES);
        cudaFuncSetAttribute(proj3_kernel,
            cudaFuncAttributeMaxDynamicSharedMemorySize, P3_SMEM);
        cudaFuncSetAttribute(av_fn,
            cudaFuncAttributeMaxDynamicSharedMemorySize, AV_SMEM);
        cudaFuncSetAttribute(out_fn,
            cudaFuncAttributeMaxDynamicSharedMemorySize, OUT_SMEM);
        attr_done = 1;
    }

    // 0: fp32 -> fp16 conversion of inputs + weights
    Cvt7 cv;
    cv.s[0] = key;   cv.d[0] = hkey; cv.n4[0] = PROJ_ELEMS/4;
    cv.s[1] = value; cv.d[1] = hval; cv.n4[1] = PROJ_ELEMS/4;
    cv.s[2] = query; cv.d[2] = hqin; cv.n4[2] = PROJ_ELEMS/4;
    cv.s[3] = Wk;    cv.d[3] = hwk;  cv.n4[3] = WELEMS/4;
    cv.s[4] = Wv;    cv.d[4] = hwv;  cv.n4[4] = WELEMS/4;
    cv.s[5] = Wq;    cv.d[5] = hwq;  cv.n4[5] = WELEMS/4;
    cv.s[6] = Wo;    cv.d[6] = hwo;  cv.n4[6] = WELEMS/4;
    cvt7_kernel<<<dim3(512,7,1), 256>>>(cv);

    // 1: merged QKV projections
    P3 p;
    p.A[0] = hkey; p.W[0] = hwk; p.b[0] = bk; p.C[0] = pk; p.s[0] = 1.0f;
    p.A[1] = hval; p.W[1] = hwv; p.b[1] = bv; p.C[1] = pv; p.s[1] = 1.0f;
    p.A[2] = hqin; p.W[2] = hwq; p.b[2] = bq; p.C[2] = pq; p.s[2] = 0.125f;
    proj3_kernel<<<dim3(8,32,3), 512, P3_SMEM>>>(p);

    // 2: QK logits = Q·K^T
    qk_fn<<<dim3(8,8,BHN), 512, QK_SMEM>>>(
        pq, pk, nullptr, plog, DHD,
        DHD, DHD, LSEQ,
        LD, LD, LL,
        1.0f, nullptr);

    // 3: fused QR + mask + softmax(no-max) + AR
    pass2_fused<<<1024, 512, P2_SMEM_BYTES>>>(pq, rel_k, rel_v, plog, mask, pctx, pinvs);

    // 4: AV: ctx = (alpha'·V + AR') * inv_s
    av_fn<<<dim3(1,8,BHN), 512, AV_SMEM>>>(
        plog, pv, nullptr, pctx, LSEQ,
        LSEQ, DHD, DHD,
        LL, LD, LD,
        1.0f, pinvs);

    // 5: out = ctx @ Wo^T + bo
    out_fn<<<dim3(8,32,1), 512, OUT_SMEM>>>(
        pctx, hwo, bo, out, DMODEL,
        0, DMODEL, DMODEL,
        0, 0, 0,
        1.0f, nullptr);
}